// round 4
// baseline (speedup 1.0000x reference)
#include <cuda_runtime.h>
#include <cstdint>

// ---------------------------------------------------------------------------
// Problem constants
// ---------------------------------------------------------------------------
#define N_TOK   4096
#define DIM     4096
#define OUT_DIM 4096
#define NE      8
#define NH      3
#define NR      16
#define NU      384
#define K_ALL   (DIM + NU)     // 4480
#define SCALE_F 2.0f
#define NWG     256            // padded prep-weight rows
#define KSLICES 8

// Scratch (static; no runtime allocation). All K-major rows are stored with a
// 4x4 transpose permutation inside each 16-element k-group:
//   pos(k) = (k&3)*4 + ((k>>2)&3)   (self-inverse)
__device__ float g_Xr[(size_t)N_TOK * K_ALL];            // [N][4480]
__device__ float g_Wt[(size_t)OUT_DIM * K_ALL];          // [O][4480]
__device__ float g_Wg[(size_t)NWG * DIM];                // [256][4096]
__device__ float g_P4[(size_t)KSLICES * N_TOK * NWG];    // split-K partials

__device__ __forceinline__ uint32_t f2tf32(float f) {
    uint32_t u;
    asm("cvt.rna.tf32.f32 %0, %1;" : "=r"(u) : "f"(f));
    return u;
}
__device__ __forceinline__ int kperm(int k) {            // permute within 16-group
    return (k & ~15) | ((k & 3) * 4 + ((k >> 2) & 3));
}

// ---------------------------------------------------------------------------
// K1: Xr[:, 0:4096] = rna(x), k-permuted. One thread per 16-k group.
// ---------------------------------------------------------------------------
__global__ __launch_bounds__(256) void round_x_kernel(const float* __restrict__ x) {
    size_t id  = (size_t)blockIdx.x * blockDim.x + threadIdx.x;   // N*256 total
    size_t row = id >> 8;
    size_t g16 = id & 255;
    const float* src = x + row * DIM + g16 * 16;
    float4 v[4];
    #pragma unroll
    for (int q = 0; q < 4; q++) v[q] = reinterpret_cast<const float4*>(src)[q];
    float* dst = g_Xr + row * K_ALL + g16 * 16;
    #pragma unroll
    for (int p = 0; p < 4; p++) {
        float4 o;
        o.x = __uint_as_float(f2tf32((&v[0].x)[p]));
        o.y = __uint_as_float(f2tf32((&v[1].x)[p]));
        o.z = __uint_as_float(f2tf32((&v[2].x)[p]));
        o.w = __uint_as_float(f2tf32((&v[3].x)[p]));
        reinterpret_cast<float4*>(dst)[p] = o;
    }
}

// ---------------------------------------------------------------------------
// K2: Wt[n][kperm(k)] = rna( k<4096 ? baseW[k][n] : Bfl[k-4096][n] )
// ---------------------------------------------------------------------------
__global__ __launch_bounds__(256) void transpose_w_kernel(
    const float* __restrict__ baseW, const float* __restrict__ Bfl) {
    __shared__ float tile[32][33];
    const int tx = threadIdx.x & 31, ty = threadIdx.x >> 5;
    const int kb = blockIdx.x * 32, nb = blockIdx.y * 32;
    #pragma unroll
    for (int i = 0; i < 4; i++) {
        int k = kb + ty + 8 * i;
        int n = nb + tx;
        float v = (k < DIM) ? baseW[(size_t)k * OUT_DIM + n]
                            : Bfl[(size_t)(k - DIM) * OUT_DIM + n];
        tile[ty + 8 * i][tx] = __uint_as_float(f2tf32(v));
    }
    __syncthreads();
    #pragma unroll
    for (int i = 0; i < 4; i++) {
        int n = nb + ty + 8 * i;
        int k = kb + tx;
        g_Wt[(size_t)n * K_ALL + kperm(k)] = tile[tx][ty + 8 * i];
    }
}

// ---------------------------------------------------------------------------
// K3: gather Wg (k-permuted): rows 0..127 = A[e][:,r], 128..151 = Rm[e][:,h]
// ---------------------------------------------------------------------------
__global__ __launch_bounds__(256) void gather_wg_kernel(
    const float* __restrict__ A, const float* __restrict__ Rm) {
    int idx = blockIdx.x * 256 + threadIdx.x;     // 256*4096 total
    int j = idx >> 12, d = idx & 4095;
    float v = 0.f;
    if (j < 128) {
        int e = j >> 4, r = j & 15;
        v = A[((size_t)e * DIM + d) * NR + r];
    } else if (j < 152) {
        int jj = j - 128, e = jj / 3, h = jj - 3 * e;
        v = Rm[((size_t)e * DIM + d) * NH + h];
    }
    g_Wg[(size_t)j * DIM + kperm(d)] = __uint_as_float(f2tf32(v));
}

// ---------------------------------------------------------------------------
// K4: TF32 tensor GEMM  out = A[M][lda] @ B[N][ldb]^T, both K-major permuted.
// 256x128 CTA tile, 4x2 warps (64x64 each), BK=32 floats, 3-stage cp.async,
// LDS.128 fragment loads via the k-group permutation, XOR-swizzled banks.
// blockIdx.z = K-slice (A,B advanced by slice_k floats; out by out_slice).
// ---------------------------------------------------------------------------
#define BM 256
#define BN 128
#define BKF 32
#define NSTAGE 3
#define ASTG (BM * BKF * 4)    // 32 KB
#define BSTG (BN * BKF * 4)    // 16 KB
#define SMEM_GEMM (NSTAGE * (ASTG + BSTG))   // 144 KB

__device__ __forceinline__ void cp16(uint32_t daddr, const float* gptr) {
    asm volatile("cp.async.cg.shared.global [%0], [%1], 16;"
                 :: "r"(daddr), "l"(gptr) : "memory");
}
__device__ __forceinline__ uint4 lds128(uint32_t a) {
    uint4 v;
    asm volatile("ld.shared.v4.b32 {%0,%1,%2,%3}, [%4];"
                 : "=r"(v.x), "=r"(v.y), "=r"(v.z), "=r"(v.w) : "r"(a));
    return v;
}
__device__ __forceinline__ uint32_t smem_u32(const void* p) {
    uint32_t a;
    asm("{ .reg .u64 t; cvta.to.shared.u64 t, %1; cvt.u32.u64 %0, t; }" : "=r"(a) : "l"(p));
    return a;
}
__device__ __forceinline__ uint32_t swz(uint32_t v) {       // 8-granule swizzle
    return ((v & 1u) << 2) | (v >> 1);
}
__device__ __forceinline__ void mma8(float* c, uint32_t a0, uint32_t a1,
                                     uint32_t a2, uint32_t a3,
                                     uint32_t b0, uint32_t b1) {
    asm volatile(
        "mma.sync.aligned.m16n8k8.row.col.f32.tf32.tf32.f32 "
        "{%0,%1,%2,%3}, {%4,%5,%6,%7}, {%8,%9}, {%0,%1,%2,%3};\n"
        : "+f"(c[0]), "+f"(c[1]), "+f"(c[2]), "+f"(c[3])
        : "r"(a0), "r"(a1), "r"(a2), "r"(a3), "r"(b0), "r"(b1));
}

__global__ __launch_bounds__(256, 1) void mma_gemm_kernel(
    const float* __restrict__ Ag, int lda,
    const float* __restrict__ Bg, int ldb,
    float* __restrict__ out, int ldo, int ksteps,
    size_t slice_k, size_t out_slice)
{
    extern __shared__ __align__(1024) float sm[];
    const uint32_t smuA = smem_u32(sm);
    const uint32_t smuB = smuA + NSTAGE * ASTG;

    Ag  += (size_t)blockIdx.z * slice_k;
    Bg  += (size_t)blockIdx.z * slice_k;
    out += (size_t)blockIdx.z * out_slice;

    const int tid = threadIdx.x, lane = tid & 31, warp = tid >> 5;
    const int wm = warp >> 1, wn = warp & 1;          // 4 x 2 warp grid
    const int g = lane >> 2, tg = lane & 3;
    const int m0 = blockIdx.y * BM, n0 = blockIdx.x * BN;

    const int lrow = tid >> 3;                        // 0..31
    const int lkq  = tid & 7;                         // 16B granule
    const uint32_t sgr = (lkq ^ swz(lrow & 7)) * 16;  // swizzled STS granule

    float c[4][8][4];
    #pragma unroll
    for (int i = 0; i < 4; i++)
        #pragma unroll
        for (int j = 0; j < 8; j++)
            #pragma unroll
            for (int k = 0; k < 4; k++) c[i][j][k] = 0.f;

    auto issue = [&](int kt, int s) {
        const float* ab = Ag + (size_t)(m0 + lrow) * lda + (size_t)kt * BKF + lkq * 4;
        const float* bb = Bg + (size_t)(n0 + lrow) * ldb + (size_t)kt * BKF + lkq * 4;
        #pragma unroll
        for (int i = 0; i < 8; i++)
            cp16(smuA + s * ASTG + (lrow + 32 * i) * 128 + sgr,
                 ab + (size_t)(32 * i) * lda);
        #pragma unroll
        for (int i = 0; i < 4; i++)
            cp16(smuB + s * BSTG + (lrow + 32 * i) * 128 + sgr,
                 bb + (size_t)(32 * i) * ldb);
    };

    #pragma unroll
    for (int s = 0; s < NSTAGE - 1; s++) {
        issue(s, s);
        asm volatile("cp.async.commit_group;" ::: "memory");
    }

    const uint32_t fsw = swz((uint32_t)g) * 16;       // fragment granule swizzle

    for (int kt = 0; kt < ksteps; kt++) {
        const int cur = kt % NSTAGE;
        asm volatile("cp.async.wait_group %0;" :: "n"(NSTAGE - 2) : "memory");
        __syncthreads();

        int nk = kt + NSTAGE - 1;
        if (nk < ksteps) issue(nk, nk % NSTAGE);
        asm volatile("cp.async.commit_group;" ::: "memory");

        const uint32_t sA = smuA + cur * ASTG + (wm * 64 + g) * 128;
        const uint32_t sB = smuB + cur * BSTG + (wn * 64 + g) * 128;

        #pragma unroll
        for (int grp = 0; grp < 2; grp++) {
            const uint32_t goff = ((grp * 4 + tg) * 16) ^ fsw;
            uint4 alo[4], ahi[4], bv[8];
            #pragma unroll
            for (int im = 0; im < 4; im++) {
                uint32_t ra = sA + im * 16 * 128 + goff;
                alo[im] = lds128(ra);
                ahi[im] = lds128(ra + 8 * 128);
            }
            #pragma unroll
            for (int in = 0; in < 8; in++)
                bv[in] = lds128(sB + in * 8 * 128 + goff);

            #pragma unroll
            for (int im = 0; im < 4; im++)
                #pragma unroll
                for (int in = 0; in < 8; in++) {
                    mma8(c[im][in], alo[im].x, ahi[im].x, alo[im].y, ahi[im].y,
                         bv[in].x, bv[in].y);
                    mma8(c[im][in], alo[im].z, ahi[im].z, alo[im].w, ahi[im].w,
                         bv[in].z, bv[in].w);
                }
        }
    }

    // epilogue (same per-thread mapping validated in R1/R3)
    #pragma unroll
    for (int im = 0; im < 4; im++) {
        int row = m0 + wm * 64 + im * 16 + g;
        #pragma unroll
        for (int in = 0; in < 8; in++) {
            int col = n0 + wn * 64 + in * 8 + 2 * tg;
            float2 v0 = make_float2(c[im][in][0], c[im][in][1]);
            float2 v1 = make_float2(c[im][in][2], c[im][in][3]);
            *reinterpret_cast<float2*>(&out[(size_t)row * ldo + col])       = v0;
            *reinterpret_cast<float2*>(&out[(size_t)(row + 8) * ldo + col]) = v1;
        }
    }
}

// ---------------------------------------------------------------------------
// K5: finalize — reduce split-K partials, exact router logits (fp32), top-2
// gates, head softmax, u -> Xr[:, 4096:] (k-permuted). 16 tokens / block.
// ---------------------------------------------------------------------------
__global__ __launch_bounds__(512) void finalize_kernel(
    const float* __restrict__ x, const float* __restrict__ routerW)
{
    extern __shared__ float rw[];               // [NE * DIM] = 128KB
    __shared__ float scoeff[16][24];
    __shared__ float sP[16][160];

    const int tid = threadIdx.x, lane = tid & 31, warp = tid >> 5;
    const int token = blockIdx.x * 16 + warp;

    for (int i = tid; i < NE * DIM / 4; i += 512)
        reinterpret_cast<float4*>(rw)[i] = reinterpret_cast<const float4*>(routerW)[i];

    // reduce split-K partials for this token's prep row (cols 0..159)
    #pragma unroll
    for (int rep = 0; rep < 5; rep++) {
        int idx = lane + 32 * rep;
        float s = 0.f;
        #pragma unroll
        for (int sl = 0; sl < KSLICES; sl++)
            s += g_P4[((size_t)sl * N_TOK + token) * NWG + idx];
        sP[warp][idx] = s;
    }
    __syncthreads();

    // exact router logits
    float acc[NE];
    #pragma unroll
    for (int e = 0; e < NE; e++) acc[e] = 0.f;
    const float* xrow = x + (size_t)token * DIM;
    for (int i = lane; i < DIM; i += 32) {
        float xv = __ldg(xrow + i);
        #pragma unroll
        for (int e = 0; e < NE; e++) acc[e] += xv * rw[e * DIM + i];
    }
    #pragma unroll
    for (int e = 0; e < NE; e++)
        #pragma unroll
        for (int o = 16; o > 0; o >>= 1)
            acc[e] += __shfl_xor_sync(0xffffffffu, acc[e], o);

    if (lane == 0) {
        int i1 = 0;
        #pragma unroll
        for (int e = 1; e < NE; e++) if (acc[e] > acc[i1]) i1 = e;
        int i2 = (i1 == 0) ? 1 : 0;
        #pragma unroll
        for (int e = 0; e < NE; e++)
            if (e != i1 && acc[e] > acc[i2]) i2 = e;

        float ed = expf(acc[i2] - acc[i1]);
        float g1 = 1.f / (1.f + ed);
        float g2 = ed / (1.f + ed);

        #pragma unroll
        for (int q = 0; q < 24; q++) scoeff[warp][q] = 0.f;

        int   ids[2] = {i1, i2};
        float gs[2]  = {g1, g2};
        #pragma unroll
        for (int p = 0; p < 2; p++) {
            int e = ids[p];
            float h0 = sP[warp][128 + e * 3 + 0];
            float h1 = sP[warp][128 + e * 3 + 1];
            float h2 = sP[warp][128 + e * 3 + 2];
            float m  = fmaxf(h0, fmaxf(h1, h2));
            float x0 = expf(h0 - m), x1 = expf(h1 - m), x2 = expf(h2 - m);
            float inv = gs[p] * SCALE_F / (x0 + x1 + x2);
            scoeff[warp][e * 3 + 0] = x0 * inv;
            scoeff[warp][e * 3 + 1] = x1 * inv;
            scoeff[warp][e * 3 + 2] = x2 * inv;
        }
    }
    __syncwarp();

    #pragma unroll
    for (int rep = 0; rep < NU / 32; rep++) {
        int j = lane + 32 * rep;             // 0..383
        int e = j / 48;
        int jr = j - e * 48;
        int h = jr >> 4, r = jr & 15;
        float u = scoeff[warp][e * 3 + h] * sP[warp][e * 16 + r];
        g_Xr[(size_t)token * K_ALL + DIM + kperm(j)] = __uint_as_float(f2tf32(u));
    }
}

// ---------------------------------------------------------------------------
// host launch
// ---------------------------------------------------------------------------
extern "C" void kernel_launch(void* const* d_in, const int* in_sizes, int n_in,
                              void* d_out, int out_size) {
    const float* x       = (const float*)d_in[0];
    const float* baseW   = (const float*)d_in[1];
    const float* routerW = (const float*)d_in[2];
    const float* A       = (const float*)d_in[3];
    const float* B       = (const float*)d_in[4];
    const float* Rm      = (const float*)d_in[5];
    float* out = (float*)d_out;

    void *pXr = nullptr, *pWt = nullptr, *pWg = nullptr, *pP4 = nullptr;
    cudaGetSymbolAddress(&pXr, g_Xr);
    cudaGetSymbolAddress(&pWt, g_Wt);
    cudaGetSymbolAddress(&pWg, g_Wg);
    cudaGetSymbolAddress(&pP4, g_P4);

    static bool attr_set = false;
    if (!attr_set) {
        cudaFuncSetAttribute(mma_gemm_kernel,
                             cudaFuncAttributeMaxDynamicSharedMemorySize, SMEM_GEMM);
        cudaFuncSetAttribute(finalize_kernel,
                             cudaFuncAttributeMaxDynamicSharedMemorySize,
                             NE * DIM * sizeof(float));
        attr_set = true;
    }

    // 1) rna(x) -> Xr[:, :4096] (k-permuted)
    round_x_kernel<<<(N_TOK * 256) / 256, 256>>>(x);
    // 2) rna([baseW;Bfl]^T) -> Wt
    transpose_w_kernel<<<dim3(K_ALL / 32, OUT_DIM / 32), 256>>>(baseW, B);
    // 3) gathered prep weights -> Wg
    gather_wg_kernel<<<(NWG * DIM) / 256, 256>>>(A, Rm);
    // 4) prep GEMM, split-K=8: P4[s] = Xr[:, s-slice] @ Wg[:, s-slice]^T
    {
        int stages = DIM / BKF / KSLICES;                 // 16
        size_t slice_k = (size_t)stages * BKF;            // 512 floats
        mma_gemm_kernel<<<dim3(NWG / BN, N_TOK / BM, KSLICES), 256, SMEM_GEMM>>>(
            (const float*)pXr, K_ALL, (const float*)pWg, DIM,
            (float*)pP4, NWG, stages, slice_k, (size_t)N_TOK * NWG);
    }
    // 5) reduce partials + gates + head softmax + u -> Xr[:, 4096:]
    finalize_kernel<<<N_TOK / 16, 512, NE * DIM * sizeof(float)>>>(x, routerW);
    // 6) main GEMM: out = Xr @ Wt^T
    mma_gemm_kernel<<<dim3(OUT_DIM / BN, N_TOK / BM, 1), 256, SMEM_GEMM>>>(
        (const float*)pXr, K_ALL, (const float*)pWt, K_ALL,
        out, OUT_DIM, K_ALL / BKF, 0, 0);
}

// round 5
// speedup vs baseline: 1.1348x; 1.1348x over previous
#include <cuda_runtime.h>
#include <cstdint>

// ---------------------------------------------------------------------------
// Problem constants
// ---------------------------------------------------------------------------
#define N_TOK   4096
#define DIM     4096
#define OUT_DIM 4096
#define NE      8
#define NH      3
#define NR      16
#define NU      384
#define K_ALL   (DIM + NU)     // 4480
#define SCALE_F 2.0f
#define NWG     256            // padded prep-weight rows
#define KSLICES 8

// Scratch (static; no runtime allocation). K-major rows stored with a 4x4
// transpose permutation inside each 16-element k-group:
//   pos(k) = (k&3)*4 + ((k>>2)&3)   (self-inverse)
__device__ float g_Xr[(size_t)N_TOK * K_ALL];            // [N][4480]
__device__ float g_Wt[(size_t)OUT_DIM * K_ALL];          // [O][4480]
__device__ float g_Wg[(size_t)NWG * DIM];                // [256][4096]
__device__ float g_P4[(size_t)KSLICES * N_TOK * NWG];    // split-K partials

__device__ __forceinline__ uint32_t f2tf32(float f) {
    uint32_t u;
    asm("cvt.rna.tf32.f32 %0, %1;" : "=r"(u) : "f"(f));
    return u;
}
__device__ __forceinline__ int kperm(int k) {
    return (k & ~15) | ((k & 3) * 4 + ((k >> 2) & 3));
}

// ---------------------------------------------------------------------------
// K1: Xr[:, 0:4096] = rna(x), k-permuted. One thread per 16-k group.
// ---------------------------------------------------------------------------
__global__ __launch_bounds__(256) void round_x_kernel(const float* __restrict__ x) {
    size_t id  = (size_t)blockIdx.x * blockDim.x + threadIdx.x;   // N*256 total
    size_t row = id >> 8;
    size_t g16 = id & 255;
    const float* src = x + row * DIM + g16 * 16;
    float4 v[4];
    #pragma unroll
    for (int q = 0; q < 4; q++) v[q] = reinterpret_cast<const float4*>(src)[q];
    float* dst = g_Xr + row * K_ALL + g16 * 16;
    #pragma unroll
    for (int p = 0; p < 4; p++) {
        float4 o;
        o.x = __uint_as_float(f2tf32((&v[0].x)[p]));
        o.y = __uint_as_float(f2tf32((&v[1].x)[p]));
        o.z = __uint_as_float(f2tf32((&v[2].x)[p]));
        o.w = __uint_as_float(f2tf32((&v[3].x)[p]));
        reinterpret_cast<float4*>(dst)[p] = o;
    }
}

// ---------------------------------------------------------------------------
// K2: Wt[n][kperm(k)] = rna( k<4096 ? baseW[k][n] : Bfl[k-4096][n] )
// ---------------------------------------------------------------------------
__global__ __launch_bounds__(256) void transpose_w_kernel(
    const float* __restrict__ baseW, const float* __restrict__ Bfl) {
    __shared__ float tile[32][33];
    const int tx = threadIdx.x & 31, ty = threadIdx.x >> 5;
    const int kb = blockIdx.x * 32, nb = blockIdx.y * 32;
    #pragma unroll
    for (int i = 0; i < 4; i++) {
        int k = kb + ty + 8 * i;
        int n = nb + tx;
        float v = (k < DIM) ? baseW[(size_t)k * OUT_DIM + n]
                            : Bfl[(size_t)(k - DIM) * OUT_DIM + n];
        tile[ty + 8 * i][tx] = __uint_as_float(f2tf32(v));
    }
    __syncthreads();
    #pragma unroll
    for (int i = 0; i < 4; i++) {
        int n = nb + ty + 8 * i;
        int k = kb + tx;
        g_Wt[(size_t)n * K_ALL + kperm(k)] = tile[tx][ty + 8 * i];
    }
}

// ---------------------------------------------------------------------------
// K3: gather Wg (k-permuted): rows 0..127 = A[e][:,r], 128..151 = Rm[e][:,h]
// ---------------------------------------------------------------------------
__global__ __launch_bounds__(256) void gather_wg_kernel(
    const float* __restrict__ A, const float* __restrict__ Rm) {
    int idx = blockIdx.x * 256 + threadIdx.x;     // 256*4096 total
    int j = idx >> 12, d = idx & 4095;
    float v = 0.f;
    if (j < 128) {
        int e = j >> 4, r = j & 15;
        v = A[((size_t)e * DIM + d) * NR + r];
    } else if (j < 152) {
        int jj = j - 128, e = jj / 3, h = jj - 3 * e;
        v = Rm[((size_t)e * DIM + d) * NH + h];
    }
    g_Wg[(size_t)j * DIM + kperm(d)] = __uint_as_float(f2tf32(v));
}

// ---------------------------------------------------------------------------
// K4: TF32 tensor GEMM  out = A[M][lda] @ B[N][ldb]^T, both K-major permuted.
// 128x128 CTA tile, 2x4 warps (64x32 each), BK=32, 3-stage cp.async,
// LDS.128 fragment loads, XOR-swizzled banks, 2 CTAs/SM.
// ---------------------------------------------------------------------------
#define BM 128
#define BN 128
#define BKF 32
#define NSTAGE 3
#define ASTG (BM * BKF * 4)    // 16 KB
#define BSTG (BN * BKF * 4)    // 16 KB
#define SMEM_GEMM (NSTAGE * (ASTG + BSTG))   // 96 KB

__device__ __forceinline__ void cp16(uint32_t daddr, const float* gptr) {
    asm volatile("cp.async.cg.shared.global [%0], [%1], 16;"
                 :: "r"(daddr), "l"(gptr) : "memory");
}
__device__ __forceinline__ uint4 lds128(uint32_t a) {
    uint4 v;
    asm volatile("ld.shared.v4.b32 {%0,%1,%2,%3}, [%4];"
                 : "=r"(v.x), "=r"(v.y), "=r"(v.z), "=r"(v.w) : "r"(a));
    return v;
}
__device__ __forceinline__ uint32_t smem_u32(const void* p) {
    uint32_t a;
    asm("{ .reg .u64 t; cvta.to.shared.u64 t, %1; cvt.u32.u64 %0, t; }" : "=r"(a) : "l"(p));
    return a;
}
__device__ __forceinline__ uint32_t swz(uint32_t v) {       // bijection on 0..7
    return ((v & 1u) << 2) | (v >> 1);
}
__device__ __forceinline__ void mma8(float* c, uint32_t a0, uint32_t a1,
                                     uint32_t a2, uint32_t a3,
                                     uint32_t b0, uint32_t b1) {
    asm volatile(
        "mma.sync.aligned.m16n8k8.row.col.f32.tf32.tf32.f32 "
        "{%0,%1,%2,%3}, {%4,%5,%6,%7}, {%8,%9}, {%0,%1,%2,%3};\n"
        : "+f"(c[0]), "+f"(c[1]), "+f"(c[2]), "+f"(c[3])
        : "r"(a0), "r"(a1), "r"(a2), "r"(a3), "r"(b0), "r"(b1));
}

__global__ __launch_bounds__(256, 2) void mma_gemm_kernel(
    const float* __restrict__ Ag, int lda,
    const float* __restrict__ Bg, int ldb,
    float* __restrict__ out, int ldo, int ksteps,
    size_t slice_k, size_t out_slice)
{
    extern __shared__ __align__(1024) float sm[];
    const uint32_t smuA = smem_u32(sm);
    const uint32_t smuB = smuA + NSTAGE * ASTG;

    Ag  += (size_t)blockIdx.z * slice_k;
    Bg  += (size_t)blockIdx.z * slice_k;
    out += (size_t)blockIdx.z * out_slice;

    const int tid = threadIdx.x, lane = tid & 31, warp = tid >> 5;
    const int wm = warp & 1, wn = warp >> 1;          // 2 x 4 warp grid
    const int g = lane >> 2, tg = lane & 3;
    const int m0 = blockIdx.y * BM, n0 = blockIdx.x * BN;

    const int lrow = tid >> 3;                        // 0..31
    const int lkq  = tid & 7;                         // 16B granule
    const uint32_t sgr = (lkq ^ swz(lrow & 7)) * 16;  // swizzled STS granule

    float c[4][4][4];
    #pragma unroll
    for (int i = 0; i < 4; i++)
        #pragma unroll
        for (int j = 0; j < 4; j++)
            #pragma unroll
            for (int k = 0; k < 4; k++) c[i][j][k] = 0.f;

    auto issue = [&](int kt, int s) {
        const float* ab = Ag + (size_t)(m0 + lrow) * lda + (size_t)kt * BKF + lkq * 4;
        const float* bb = Bg + (size_t)(n0 + lrow) * ldb + (size_t)kt * BKF + lkq * 4;
        #pragma unroll
        for (int i = 0; i < 4; i++)
            cp16(smuA + s * ASTG + (lrow + 32 * i) * 128 + sgr,
                 ab + (size_t)(32 * i) * lda);
        #pragma unroll
        for (int i = 0; i < 4; i++)
            cp16(smuB + s * BSTG + (lrow + 32 * i) * 128 + sgr,
                 bb + (size_t)(32 * i) * ldb);
    };

    #pragma unroll
    for (int s = 0; s < NSTAGE - 1; s++) {
        issue(s, s);
        asm volatile("cp.async.commit_group;" ::: "memory");
    }

    const uint32_t fsw = swz((uint32_t)g) * 16;       // fragment granule swizzle

    for (int kt = 0; kt < ksteps; kt++) {
        const int cur = kt % NSTAGE;
        asm volatile("cp.async.wait_group %0;" :: "n"(NSTAGE - 2) : "memory");
        __syncthreads();

        int nk = kt + NSTAGE - 1;
        if (nk < ksteps) issue(nk, nk % NSTAGE);
        asm volatile("cp.async.commit_group;" ::: "memory");

        const uint32_t sA = smuA + cur * ASTG + (wm * 64 + g) * 128;
        const uint32_t sB = smuB + cur * BSTG + (wn * 32 + g) * 128;

        #pragma unroll
        for (int grp = 0; grp < 2; grp++) {
            const uint32_t goff = ((grp * 4 + tg) * 16) ^ fsw;
            uint4 alo[4], ahi[4], bv[4];
            #pragma unroll
            for (int im = 0; im < 4; im++) {
                uint32_t ra = sA + im * 16 * 128 + goff;
                alo[im] = lds128(ra);
                ahi[im] = lds128(ra + 8 * 128);
            }
            #pragma unroll
            for (int in = 0; in < 4; in++)
                bv[in] = lds128(sB + in * 8 * 128 + goff);

            #pragma unroll
            for (int im = 0; im < 4; im++)
                #pragma unroll
                for (int in = 0; in < 4; in++) {
                    mma8(c[im][in], alo[im].x, ahi[im].x, alo[im].y, ahi[im].y,
                         bv[in].x, bv[in].y);
                    mma8(c[im][in], alo[im].z, ahi[im].z, alo[im].w, ahi[im].w,
                         bv[in].z, bv[in].w);
                }
        }
    }

    // epilogue (per-thread mapping validated R1/R3/R4)
    #pragma unroll
    for (int im = 0; im < 4; im++) {
        int row = m0 + wm * 64 + im * 16 + g;
        #pragma unroll
        for (int in = 0; in < 4; in++) {
            int col = n0 + wn * 32 + in * 8 + 2 * tg;
            float2 v0 = make_float2(c[im][in][0], c[im][in][1]);
            float2 v1 = make_float2(c[im][in][2], c[im][in][3]);
            *reinterpret_cast<float2*>(&out[(size_t)row * ldo + col])       = v0;
            *reinterpret_cast<float2*>(&out[(size_t)(row + 8) * ldo + col]) = v1;
        }
    }
}

// ---------------------------------------------------------------------------
// K5: finalize — reduce split-K partials, exact router logits (fp32), top-2
// gates, head softmax, u -> Xr[:, 4096:] (k-permuted). 16 tokens / block.
// ---------------------------------------------------------------------------
__global__ __launch_bounds__(512) void finalize_kernel(
    const float* __restrict__ x, const float* __restrict__ routerW)
{
    extern __shared__ float rw[];               // [NE * DIM] = 128KB
    __shared__ float scoeff[16][24];
    __shared__ float sP[16][160];

    const int tid = threadIdx.x, lane = tid & 31, warp = tid >> 5;
    const int token = blockIdx.x * 16 + warp;

    for (int i = tid; i < NE * DIM / 4; i += 512)
        reinterpret_cast<float4*>(rw)[i] = reinterpret_cast<const float4*>(routerW)[i];

    // reduce split-K partials for this token's prep row (cols 0..159)
    #pragma unroll
    for (int rep = 0; rep < 5; rep++) {
        int idx = lane + 32 * rep;
        float s = 0.f;
        #pragma unroll
        for (int sl = 0; sl < KSLICES; sl++)
            s += g_P4[((size_t)sl * N_TOK + token) * NWG + idx];
        sP[warp][idx] = s;
    }
    __syncthreads();

    // exact router logits
    float acc[NE];
    #pragma unroll
    for (int e = 0; e < NE; e++) acc[e] = 0.f;
    const float* xrow = x + (size_t)token * DIM;
    for (int i = lane; i < DIM; i += 32) {
        float xv = __ldg(xrow + i);
        #pragma unroll
        for (int e = 0; e < NE; e++) acc[e] += xv * rw[e * DIM + i];
    }
    #pragma unroll
    for (int e = 0; e < NE; e++)
        #pragma unroll
        for (int o = 16; o > 0; o >>= 1)
            acc[e] += __shfl_xor_sync(0xffffffffu, acc[e], o);

    if (lane == 0) {
        int i1 = 0;
        #pragma unroll
        for (int e = 1; e < NE; e++) if (acc[e] > acc[i1]) i1 = e;
        int i2 = (i1 == 0) ? 1 : 0;
        #pragma unroll
        for (int e = 0; e < NE; e++)
            if (e != i1 && acc[e] > acc[i2]) i2 = e;

        float ed = expf(acc[i2] - acc[i1]);
        float g1 = 1.f / (1.f + ed);
        float g2 = ed / (1.f + ed);

        #pragma unroll
        for (int q = 0; q < 24; q++) scoeff[warp][q] = 0.f;

        int   ids[2] = {i1, i2};
        float gs[2]  = {g1, g2};
        #pragma unroll
        for (int p = 0; p < 2; p++) {
            int e = ids[p];
            float h0 = sP[warp][128 + e * 3 + 0];
            float h1 = sP[warp][128 + e * 3 + 1];
            float h2 = sP[warp][128 + e * 3 + 2];
            float m  = fmaxf(h0, fmaxf(h1, h2));
            float x0 = expf(h0 - m), x1 = expf(h1 - m), x2 = expf(h2 - m);
            float inv = gs[p] * SCALE_F / (x0 + x1 + x2);
            scoeff[warp][e * 3 + 0] = x0 * inv;
            scoeff[warp][e * 3 + 1] = x1 * inv;
            scoeff[warp][e * 3 + 2] = x2 * inv;
        }
    }
    __syncwarp();

    #pragma unroll
    for (int rep = 0; rep < NU / 32; rep++) {
        int j = lane + 32 * rep;             // 0..383
        int e = j / 48;
        int jr = j - e * 48;
        int h = jr >> 4, r = jr & 15;
        float u = scoeff[warp][e * 3 + h] * sP[warp][e * 16 + r];
        g_Xr[(size_t)token * K_ALL + DIM + kperm(j)] = __uint_as_float(f2tf32(u));
    }
}

// ---------------------------------------------------------------------------
// host launch
// ---------------------------------------------------------------------------
extern "C" void kernel_launch(void* const* d_in, const int* in_sizes, int n_in,
                              void* d_out, int out_size) {
    const float* x       = (const float*)d_in[0];
    const float* baseW   = (const float*)d_in[1];
    const float* routerW = (const float*)d_in[2];
    const float* A       = (const float*)d_in[3];
    const float* B       = (const float*)d_in[4];
    const float* Rm      = (const float*)d_in[5];
    float* out = (float*)d_out;

    void *pXr = nullptr, *pWt = nullptr, *pWg = nullptr, *pP4 = nullptr;
    cudaGetSymbolAddress(&pXr, g_Xr);
    cudaGetSymbolAddress(&pWt, g_Wt);
    cudaGetSymbolAddress(&pWg, g_Wg);
    cudaGetSymbolAddress(&pP4, g_P4);

    static bool attr_set = false;
    if (!attr_set) {
        cudaFuncSetAttribute(mma_gemm_kernel,
                             cudaFuncAttributeMaxDynamicSharedMemorySize, SMEM_GEMM);
        cudaFuncSetAttribute(finalize_kernel,
                             cudaFuncAttributeMaxDynamicSharedMemorySize,
                             NE * DIM * sizeof(float));
        attr_set = true;
    }

    // 1) rna(x) -> Xr[:, :4096] (k-permuted)
    round_x_kernel<<<(N_TOK * 256) / 256, 256>>>(x);
    // 2) rna([baseW;Bfl]^T) -> Wt
    transpose_w_kernel<<<dim3(K_ALL / 32, OUT_DIM / 32), 256>>>(baseW, B);
    // 3) gathered prep weights -> Wg
    gather_wg_kernel<<<(NWG * DIM) / 256, 256>>>(A, Rm);
    // 4) prep GEMM, split-K=8: P4[s] = Xr[:, s-slice] @ Wg[:, s-slice]^T
    {
        int stages = DIM / BKF / KSLICES;                 // 16
        size_t slice_k = (size_t)stages * BKF;            // 512 floats
        mma_gemm_kernel<<<dim3(NWG / BN, N_TOK / BM, KSLICES), 256, SMEM_GEMM>>>(
            (const float*)pXr, K_ALL, (const float*)pWg, DIM,
            (float*)pP4, NWG, stages, slice_k, (size_t)N_TOK * NWG);
    }
    // 5) reduce partials + gates + head softmax + u -> Xr[:, 4096:]
    finalize_kernel<<<N_TOK / 16, 512, NE * DIM * sizeof(float)>>>(x, routerW);
    // 6) main GEMM: out = Xr @ Wt^T
    mma_gemm_kernel<<<dim3(OUT_DIM / BN, N_TOK / BM, 1), 256, SMEM_GEMM>>>(
        (const float*)pXr, K_ALL, (const float*)pWt, K_ALL,
        out, OUT_DIM, K_ALL / BKF, 0, 0);
}

// round 6
// speedup vs baseline: 1.9940x; 1.7571x over previous
#include <cuda_runtime.h>
#include <cuda_fp16.h>
#include <cstdint>

// ---------------------------------------------------------------------------
// Problem constants
// ---------------------------------------------------------------------------
#define N_TOK   4096
#define DIM     4096
#define OUT_DIM 4096
#define NE      8
#define NH      3
#define NR      16
#define NU      384
#define K_ALL   (DIM + NU)     // 4480
#define SCALE_F 2.0f
#define NWG     256            // padded prep-weight rows
#define KSLICES 8

// Scratch (static). Rows are K-major fp16 with a permutation inside each
// 32-element k-group: pos(k) = ((k>>1)&3)*8 + ((k>>3)&3)*2 + (k&1)
// so thread tg's mma fragments {2tg,2tg+1,2tg+8,2tg+9,2tg+16,...} are one 16B load.
__device__ __half g_Xh[(size_t)N_TOK * K_ALL];           // [N][4480] rn(x) | rn(u)
__device__ __half g_Wh[(size_t)OUT_DIM * K_ALL];         // [O][4480] rn([baseW;Bfl]^T)
__device__ __half g_Wgh[(size_t)NWG * DIM];              // [256][4096] gathered A,R
__device__ float  g_P4[(size_t)KSLICES * N_TOK * NWG];   // split-K partials (fp32)

__device__ __forceinline__ int hperm32(int k) {          // position within 32-group
    return ((k >> 1) & 3) * 8 + ((k >> 3) & 3) * 2 + (k & 1);
}
__device__ __forceinline__ int hperm(int k) {
    return (k & ~31) | hperm32(k & 31);
}
__device__ __forceinline__ int hperm_inv(int p) {        // k for position p
    return (p & 1) + 2 * (p >> 3) + 8 * ((p >> 1) & 1) + 16 * ((p >> 2) & 1);
}

// ---------------------------------------------------------------------------
// K1: Xh[:, 0:4096] = rn_f16(x), permuted. One thread per 32-k chunk.
// ---------------------------------------------------------------------------
__global__ __launch_bounds__(256) void round_x_kernel(const float* __restrict__ x) {
    size_t id  = (size_t)blockIdx.x * blockDim.x + threadIdx.x;   // N*128 total
    size_t row = id >> 7;
    size_t ch  = id & 127;
    const float* src = x + row * DIM + ch * 32;
    float4 v[8];
    #pragma unroll
    for (int q = 0; q < 8; q++) v[q] = reinterpret_cast<const float4*>(src)[q];
    __half tmp[32];
    #pragma unroll
    for (int p = 0; p < 32; p++) {
        int k = hperm_inv(p);
        tmp[p] = __float2half_rn((&v[k >> 2].x)[k & 3]);
    }
    uint4* dst = reinterpret_cast<uint4*>(g_Xh + row * K_ALL + ch * 32);
    const uint4* tp = reinterpret_cast<const uint4*>(tmp);
    #pragma unroll
    for (int q = 0; q < 4; q++) dst[q] = tp[q];
}

// ---------------------------------------------------------------------------
// K2: Wh[n][hperm(k)] = rn_f16( k<4096 ? baseW[k][n] : Bfl[k-4096][n] )
// ---------------------------------------------------------------------------
__global__ __launch_bounds__(256) void transpose_w_kernel(
    const float* __restrict__ baseW, const float* __restrict__ Bfl) {
    __shared__ float tile[32][33];
    const int tx = threadIdx.x & 31, ty = threadIdx.x >> 5;
    const int kb = blockIdx.x * 32, nb = blockIdx.y * 32;
    #pragma unroll
    for (int i = 0; i < 4; i++) {
        int k = kb + ty + 8 * i;
        int n = nb + tx;
        float v = (k < DIM) ? baseW[(size_t)k * OUT_DIM + n]
                            : Bfl[(size_t)(k - DIM) * OUT_DIM + n];
        tile[ty + 8 * i][tx] = v;
    }
    __syncthreads();
    #pragma unroll
    for (int i = 0; i < 4; i++) {
        int n = nb + ty + 8 * i;
        int k = kb + tx;
        g_Wh[(size_t)n * K_ALL + hperm(k)] = __float2half_rn(tile[tx][ty + 8 * i]);
    }
}

// ---------------------------------------------------------------------------
// K3: gather Wgh (permuted): rows 0..127 = A[e][:,r], 128..151 = Rm[e][:,h]
// ---------------------------------------------------------------------------
__global__ __launch_bounds__(256) void gather_wg_kernel(
    const float* __restrict__ A, const float* __restrict__ Rm) {
    int idx = blockIdx.x * 256 + threadIdx.x;     // 256*4096 total
    int j = idx >> 12, d = idx & 4095;
    float v = 0.f;
    if (j < 128) {
        int e = j >> 4, r = j & 15;
        v = A[((size_t)e * DIM + d) * NR + r];
    } else if (j < 152) {
        int jj = j - 128, e = jj / 3, h = jj - 3 * e;
        v = Rm[((size_t)e * DIM + d) * NH + h];
    }
    g_Wgh[(size_t)j * DIM + hperm(d)] = __float2half_rn(v);
}

// ---------------------------------------------------------------------------
// K4: FP16 tensor GEMM (fp32 accum)  out = A[M][lda] @ B[N][ldb]^T.
// 128x128 CTA tile, 2x4 warps (64x32), BK=64 halves (128B rows), 3-stage
// cp.async, LDS.128 fragments via the 32-k permutation, XOR bank swizzle,
// 2 CTAs/SM. mma.sync m16n8k16.f16 with f32 accumulators.
// ---------------------------------------------------------------------------
#define BM 128
#define BN 128
#define BKH 64                 // halves per stage-row (128 bytes)
#define NSTAGE 3
#define ASTG (BM * 128)        // 16 KB
#define BSTG (BN * 128)        // 16 KB
#define SMEM_GEMM (NSTAGE * (ASTG + BSTG))   // 96 KB

__device__ __forceinline__ void cp16(uint32_t daddr, const void* gptr) {
    asm volatile("cp.async.cg.shared.global [%0], [%1], 16;"
                 :: "r"(daddr), "l"(gptr) : "memory");
}
__device__ __forceinline__ uint4 lds128(uint32_t a) {
    uint4 v;
    asm volatile("ld.shared.v4.b32 {%0,%1,%2,%3}, [%4];"
                 : "=r"(v.x), "=r"(v.y), "=r"(v.z), "=r"(v.w) : "r"(a));
    return v;
}
__device__ __forceinline__ uint32_t smem_u32(const void* p) {
    uint32_t a;
    asm("{ .reg .u64 t; cvta.to.shared.u64 t, %1; cvt.u32.u64 %0, t; }" : "=r"(a) : "l"(p));
    return a;
}
__device__ __forceinline__ uint32_t swz(uint32_t v) {       // bijection on 0..7
    return ((v & 1u) << 2) | (v >> 1);
}
__device__ __forceinline__ void mma16(float* c, uint32_t a0, uint32_t a1,
                                      uint32_t a2, uint32_t a3,
                                      uint32_t b0, uint32_t b1) {
    asm volatile(
        "mma.sync.aligned.m16n8k16.row.col.f32.f16.f16.f32 "
        "{%0,%1,%2,%3}, {%4,%5,%6,%7}, {%8,%9}, {%0,%1,%2,%3};\n"
        : "+f"(c[0]), "+f"(c[1]), "+f"(c[2]), "+f"(c[3])
        : "r"(a0), "r"(a1), "r"(a2), "r"(a3), "r"(b0), "r"(b1));
}

__global__ __launch_bounds__(256, 2) void mma_gemm_kernel(
    const __half* __restrict__ Ag, int lda,
    const __half* __restrict__ Bg, int ldb,
    float* __restrict__ out, int ldo, int ksteps,
    size_t slice_k, size_t out_slice)
{
    extern __shared__ __align__(1024) char sm[];
    const uint32_t smuA = smem_u32(sm);
    const uint32_t smuB = smuA + NSTAGE * ASTG;

    Ag  += (size_t)blockIdx.z * slice_k;
    Bg  += (size_t)blockIdx.z * slice_k;
    out += (size_t)blockIdx.z * out_slice;

    const int tid = threadIdx.x, lane = tid & 31, warp = tid >> 5;
    const int wm = warp & 1, wn = warp >> 1;          // 2 x 4 warp grid
    const int g = lane >> 2, tg = lane & 3;
    const int m0 = blockIdx.y * BM, n0 = blockIdx.x * BN;

    const int lrow = tid >> 3;                        // 0..31
    const int lkq  = tid & 7;                         // 16B granule in 128B row
    const uint32_t sgr = (lkq ^ swz(lrow & 7)) * 16;  // swizzled STS granule

    float c[4][4][4];
    #pragma unroll
    for (int i = 0; i < 4; i++)
        #pragma unroll
        for (int j = 0; j < 4; j++)
            #pragma unroll
            for (int k = 0; k < 4; k++) c[i][j][k] = 0.f;

    auto issue = [&](int kt, int s) {
        const __half* ab = Ag + (size_t)(m0 + lrow) * lda + (size_t)kt * BKH + lkq * 8;
        const __half* bb = Bg + (size_t)(n0 + lrow) * ldb + (size_t)kt * BKH + lkq * 8;
        #pragma unroll
        for (int i = 0; i < 4; i++)
            cp16(smuA + s * ASTG + (lrow + 32 * i) * 128 + sgr,
                 ab + (size_t)(32 * i) * lda);
        #pragma unroll
        for (int i = 0; i < 4; i++)
            cp16(smuB + s * BSTG + (lrow + 32 * i) * 128 + sgr,
                 bb + (size_t)(32 * i) * ldb);
    };

    #pragma unroll
    for (int s = 0; s < NSTAGE - 1; s++) {
        issue(s, s);
        asm volatile("cp.async.commit_group;" ::: "memory");
    }

    const uint32_t fsw = swz((uint32_t)g) * 16;       // fragment granule swizzle

    for (int kt = 0; kt < ksteps; kt++) {
        const int cur = kt % NSTAGE;
        asm volatile("cp.async.wait_group %0;" :: "n"(NSTAGE - 2) : "memory");
        __syncthreads();

        int nk = kt + NSTAGE - 1;
        if (nk < ksteps) issue(nk, nk % NSTAGE);
        asm volatile("cp.async.commit_group;" ::: "memory");

        const uint32_t sA = smuA + cur * ASTG + (wm * 64 + g) * 128;
        const uint32_t sB = smuB + cur * BSTG + (wn * 32 + g) * 128;

        // two k32 chunks per 128B stage row
        #pragma unroll
        for (int chk = 0; chk < 2; chk++) {
            const uint32_t goff = ((chk * 4 + tg) * 16) ^ fsw;
            uint4 alo[4], ahi[4], bv[4];
            #pragma unroll
            for (int im = 0; im < 4; im++) {
                uint32_t ra = sA + im * 16 * 128 + goff;
                alo[im] = lds128(ra);
                ahi[im] = lds128(ra + 8 * 128);
            }
            #pragma unroll
            for (int in = 0; in < 4; in++)
                bv[in] = lds128(sB + in * 8 * 128 + goff);

            // each uint4 covers two k16 groups: (.x,.y) and (.z,.w)
            #pragma unroll
            for (int im = 0; im < 4; im++)
                #pragma unroll
                for (int in = 0; in < 4; in++) {
                    mma16(c[im][in], alo[im].x, ahi[im].x, alo[im].y, ahi[im].y,
                          bv[in].x, bv[in].y);
                    mma16(c[im][in], alo[im].z, ahi[im].z, alo[im].w, ahi[im].w,
                          bv[in].z, bv[in].w);
                }
        }
    }

    // epilogue (per-thread mapping validated R1/R3/R4/R5)
    #pragma unroll
    for (int im = 0; im < 4; im++) {
        int row = m0 + wm * 64 + im * 16 + g;
        #pragma unroll
        for (int in = 0; in < 4; in++) {
            int col = n0 + wn * 32 + in * 8 + 2 * tg;
            float2 v0 = make_float2(c[im][in][0], c[im][in][1]);
            float2 v1 = make_float2(c[im][in][2], c[im][in][3]);
            *reinterpret_cast<float2*>(&out[(size_t)row * ldo + col])       = v0;
            *reinterpret_cast<float2*>(&out[(size_t)(row + 8) * ldo + col]) = v1;
        }
    }
}

// ---------------------------------------------------------------------------
// K5: finalize — reduce split-K partials, exact fp32 router logits, top-2
// gates, head softmax, u -> Xh[:, 4096:] (permuted). 16 tokens / block.
// ---------------------------------------------------------------------------
__global__ __launch_bounds__(512) void finalize_kernel(
    const float* __restrict__ x, const float* __restrict__ routerW)
{
    extern __shared__ float rw[];               // [NE * DIM] = 128KB
    __shared__ float scoeff[16][24];
    __shared__ float sP[16][160];

    const int tid = threadIdx.x, lane = tid & 31, warp = tid >> 5;
    const int token = blockIdx.x * 16 + warp;

    for (int i = tid; i < NE * DIM / 4; i += 512)
        reinterpret_cast<float4*>(rw)[i] = reinterpret_cast<const float4*>(routerW)[i];

    #pragma unroll
    for (int rep = 0; rep < 5; rep++) {
        int idx = lane + 32 * rep;
        float s = 0.f;
        #pragma unroll
        for (int sl = 0; sl < KSLICES; sl++)
            s += g_P4[((size_t)sl * N_TOK + token) * NWG + idx];
        sP[warp][idx] = s;
    }
    __syncthreads();

    float acc[NE];
    #pragma unroll
    for (int e = 0; e < NE; e++) acc[e] = 0.f;
    const float* xrow = x + (size_t)token * DIM;
    for (int i = lane; i < DIM; i += 32) {
        float xv = __ldg(xrow + i);
        #pragma unroll
        for (int e = 0; e < NE; e++) acc[e] += xv * rw[e * DIM + i];
    }
    #pragma unroll
    for (int e = 0; e < NE; e++)
        #pragma unroll
        for (int o = 16; o > 0; o >>= 1)
            acc[e] += __shfl_xor_sync(0xffffffffu, acc[e], o);

    if (lane == 0) {
        int i1 = 0;
        #pragma unroll
        for (int e = 1; e < NE; e++) if (acc[e] > acc[i1]) i1 = e;
        int i2 = (i1 == 0) ? 1 : 0;
        #pragma unroll
        for (int e = 0; e < NE; e++)
            if (e != i1 && acc[e] > acc[i2]) i2 = e;

        float ed = expf(acc[i2] - acc[i1]);
        float g1 = 1.f / (1.f + ed);
        float g2 = ed / (1.f + ed);

        #pragma unroll
        for (int q = 0; q < 24; q++) scoeff[warp][q] = 0.f;

        int   ids[2] = {i1, i2};
        float gs[2]  = {g1, g2};
        #pragma unroll
        for (int p = 0; p < 2; p++) {
            int e = ids[p];
            float h0 = sP[warp][128 + e * 3 + 0];
            float h1 = sP[warp][128 + e * 3 + 1];
            float h2 = sP[warp][128 + e * 3 + 2];
            float m  = fmaxf(h0, fmaxf(h1, h2));
            float x0 = expf(h0 - m), x1 = expf(h1 - m), x2 = expf(h2 - m);
            float inv = gs[p] * SCALE_F / (x0 + x1 + x2);
            scoeff[warp][e * 3 + 0] = x0 * inv;
            scoeff[warp][e * 3 + 1] = x1 * inv;
            scoeff[warp][e * 3 + 2] = x2 * inv;
        }
    }
    __syncwarp();

    #pragma unroll
    for (int rep = 0; rep < NU / 32; rep++) {
        int j = lane + 32 * rep;             // 0..383 (32-aligned groups)
        int e = j / 48;
        int jr = j - e * 48;
        int h = jr >> 4, r = jr & 15;
        float u = scoeff[warp][e * 3 + h] * sP[warp][e * 16 + r];
        g_Xh[(size_t)token * K_ALL + DIM + (j & ~31) + hperm32(j & 31)] =
            __float2half_rn(u);
    }
}

// ---------------------------------------------------------------------------
// host launch
// ---------------------------------------------------------------------------
extern "C" void kernel_launch(void* const* d_in, const int* in_sizes, int n_in,
                              void* d_out, int out_size) {
    const float* x       = (const float*)d_in[0];
    const float* baseW   = (const float*)d_in[1];
    const float* routerW = (const float*)d_in[2];
    const float* A       = (const float*)d_in[3];
    const float* B       = (const float*)d_in[4];
    const float* Rm      = (const float*)d_in[5];
    float* out = (float*)d_out;

    void *pXh = nullptr, *pWh = nullptr, *pWgh = nullptr, *pP4 = nullptr;
    cudaGetSymbolAddress(&pXh,  g_Xh);
    cudaGetSymbolAddress(&pWh,  g_Wh);
    cudaGetSymbolAddress(&pWgh, g_Wgh);
    cudaGetSymbolAddress(&pP4,  g_P4);

    static bool attr_set = false;
    if (!attr_set) {
        cudaFuncSetAttribute(mma_gemm_kernel,
                             cudaFuncAttributeMaxDynamicSharedMemorySize, SMEM_GEMM);
        cudaFuncSetAttribute(finalize_kernel,
                             cudaFuncAttributeMaxDynamicSharedMemorySize,
                             NE * DIM * sizeof(float));
        attr_set = true;
    }

    // 1) rn(x) -> Xh[:, :4096] (permuted fp16)
    round_x_kernel<<<(N_TOK * 128) / 256, 256>>>(x);
    // 2) rn([baseW;Bfl]^T) -> Wh
    transpose_w_kernel<<<dim3(K_ALL / 32, OUT_DIM / 32), 256>>>(baseW, B);
    // 3) gathered prep weights -> Wgh
    gather_wg_kernel<<<(NWG * DIM) / 256, 256>>>(A, Rm);
    // 4) prep GEMM, split-K=8: P4[s] = Xh[:, s-slice] @ Wgh[:, s-slice]^T
    {
        int stages = DIM / BKH / KSLICES;                 // 8
        size_t slice_k = (size_t)stages * BKH;            // 512 halves
        mma_gemm_kernel<<<dim3(NWG / BN, N_TOK / BM, KSLICES), 256, SMEM_GEMM>>>(
            (const __half*)pXh, K_ALL, (const __half*)pWgh, DIM,
            (float*)pP4, NWG, stages, slice_k, (size_t)N_TOK * NWG);
    }
    // 5) reduce partials + gates + head softmax + u -> Xh[:, 4096:]
    finalize_kernel<<<N_TOK / 16, 512, NE * DIM * sizeof(float)>>>(x, routerW);
    // 6) main GEMM: out = Xh @ Wh^T
    mma_gemm_kernel<<<dim3(OUT_DIM / BN, N_TOK / BM, 1), 256, SMEM_GEMM>>>(
        (const __half*)pXh, K_ALL, (const __half*)pWh, K_ALL,
        out, OUT_DIM, K_ALL / BKH, 0, 0);
}

// round 7
// speedup vs baseline: 2.0112x; 1.0086x over previous
#include <cuda_runtime.h>
#include <cuda_fp16.h>
#include <cstdint>

// ---------------------------------------------------------------------------
// Problem constants
// ---------------------------------------------------------------------------
#define N_TOK   4096
#define DIM     4096
#define OUT_DIM 4096
#define NE      8
#define NH      3
#define NR      16
#define NU      384
#define K_ALL   (DIM + NU)     // 4480
#define SCALE_F 2.0f
#define NWG     256            // padded prep-weight rows
#define KSLICES 8

// Scratch (static). Rows are K-major fp16 with a permutation inside each
// 32-element k-group: pos(k) = ((k>>1)&3)*8 + ((k>>3)&3)*2 + (k&1)
// so an mma thread's fragments {2tg,2tg+1,2tg+8,2tg+9,...} are one 16B load.
__device__ __half g_Xh[(size_t)N_TOK * K_ALL];           // [N][4480] rn(x) | rn(u)
__device__ __half g_Wh[(size_t)OUT_DIM * K_ALL];         // [O][4480] rn([baseW;Bfl]^T)
__device__ __half g_Wgh[(size_t)NWG * DIM];              // [256][4096] gathered A,R
__device__ float  g_P4[(size_t)KSLICES * N_TOK * NWG];   // split-K partials (fp32)

__device__ __forceinline__ int hperm32(int k) {
    return ((k >> 1) & 3) * 8 + ((k >> 3) & 3) * 2 + (k & 1);
}
__device__ __forceinline__ int hperm(int k) {
    return (k & ~31) | hperm32(k & 31);
}
__device__ __forceinline__ int hperm_inv(int p) {
    return (p & 1) + 2 * (p >> 3) + 8 * ((p >> 1) & 1) + 16 * ((p >> 2) & 1);
}

// ---------------------------------------------------------------------------
// K1: Xh[:, 0:4096] = rn_f16(x), permuted. One thread per 32-k chunk.
// ---------------------------------------------------------------------------
__global__ __launch_bounds__(256) void round_x_kernel(const float* __restrict__ x) {
    size_t id  = (size_t)blockIdx.x * blockDim.x + threadIdx.x;   // N*128 total
    size_t row = id >> 7;
    size_t ch  = id & 127;
    const float* src = x + row * DIM + ch * 32;
    float4 v[8];
    #pragma unroll
    for (int q = 0; q < 8; q++) v[q] = reinterpret_cast<const float4*>(src)[q];
    __half tmp[32];
    #pragma unroll
    for (int p = 0; p < 32; p++) {
        int k = hperm_inv(p);
        tmp[p] = __float2half_rn((&v[k >> 2].x)[k & 3]);
    }
    uint4* dst = reinterpret_cast<uint4*>(g_Xh + row * K_ALL + ch * 32);
    const uint4* tp = reinterpret_cast<const uint4*>(tmp);
    #pragma unroll
    for (int q = 0; q < 4; q++) dst[q] = tp[q];
}

// ---------------------------------------------------------------------------
// K2: Wh[n][hperm(k)] = rn_f16( k<4096 ? baseW[k][n] : Bfl[k-4096][n] )
// ---------------------------------------------------------------------------
__global__ __launch_bounds__(256) void transpose_w_kernel(
    const float* __restrict__ baseW, const float* __restrict__ Bfl) {
    __shared__ float tile[32][33];
    const int tx = threadIdx.x & 31, ty = threadIdx.x >> 5;
    const int kb = blockIdx.x * 32, nb = blockIdx.y * 32;
    #pragma unroll
    for (int i = 0; i < 4; i++) {
        int k = kb + ty + 8 * i;
        int n = nb + tx;
        float v = (k < DIM) ? baseW[(size_t)k * OUT_DIM + n]
                            : Bfl[(size_t)(k - DIM) * OUT_DIM + n];
        tile[ty + 8 * i][tx] = v;
    }
    __syncthreads();
    #pragma unroll
    for (int i = 0; i < 4; i++) {
        int n = nb + ty + 8 * i;
        int k = kb + tx;
        g_Wh[(size_t)n * K_ALL + hperm(k)] = __float2half_rn(tile[tx][ty + 8 * i]);
    }
}

// ---------------------------------------------------------------------------
// K3: gather Wgh (permuted): rows 0..127 = A[e][:,r], 128..151 = Rm[e][:,h]
// ---------------------------------------------------------------------------
__global__ __launch_bounds__(256) void gather_wg_kernel(
    const float* __restrict__ A, const float* __restrict__ Rm) {
    int idx = blockIdx.x * 256 + threadIdx.x;     // 256*4096 total
    int j = idx >> 12, d = idx & 4095;
    float v = 0.f;
    if (j < 128) {
        int e = j >> 4, r = j & 15;
        v = A[((size_t)e * DIM + d) * NR + r];
    } else if (j < 152) {
        int jj = j - 128, e = jj / 3, h = jj - 3 * e;
        v = Rm[((size_t)e * DIM + d) * NH + h];
    }
    g_Wgh[(size_t)j * DIM + hperm(d)] = __float2half_rn(v);
}

// ---------------------------------------------------------------------------
// K4: FP16 tensor GEMM (fp32 accum)  out = A[M][lda] @ B[N][ldb]^T.
// 128x128 CTA tile, 4 warps in 2x2 grid (64x64 each), BK=64 halves,
// 3-stage cp.async, LDS.128 fragments, XOR bank swizzle, 2 CTAs/SM.
// ---------------------------------------------------------------------------
#define BM 128
#define BN 128
#define BKH 64                 // halves per stage-row (128 bytes)
#define NSTAGE 3
#define ASTG (BM * 128)        // 16 KB
#define BSTG (BN * 128)        // 16 KB
#define SMEM_GEMM (NSTAGE * (ASTG + BSTG))   // 96 KB
#define NTHR 128

__device__ __forceinline__ void cp16(uint32_t daddr, const void* gptr) {
    asm volatile("cp.async.cg.shared.global [%0], [%1], 16;"
                 :: "r"(daddr), "l"(gptr) : "memory");
}
__device__ __forceinline__ uint4 lds128(uint32_t a) {
    uint4 v;
    asm volatile("ld.shared.v4.b32 {%0,%1,%2,%3}, [%4];"
                 : "=r"(v.x), "=r"(v.y), "=r"(v.z), "=r"(v.w) : "r"(a));
    return v;
}
__device__ __forceinline__ uint32_t smem_u32(const void* p) {
    uint32_t a;
    asm("{ .reg .u64 t; cvta.to.shared.u64 t, %1; cvt.u32.u64 %0, t; }" : "=r"(a) : "l"(p));
    return a;
}
__device__ __forceinline__ uint32_t swz(uint32_t v) {       // bijection on 0..7
    return ((v & 1u) << 2) | (v >> 1);
}
__device__ __forceinline__ void mma16(float* c, uint32_t a0, uint32_t a1,
                                      uint32_t a2, uint32_t a3,
                                      uint32_t b0, uint32_t b1) {
    asm volatile(
        "mma.sync.aligned.m16n8k16.row.col.f32.f16.f16.f32 "
        "{%0,%1,%2,%3}, {%4,%5,%6,%7}, {%8,%9}, {%0,%1,%2,%3};\n"
        : "+f"(c[0]), "+f"(c[1]), "+f"(c[2]), "+f"(c[3])
        : "r"(a0), "r"(a1), "r"(a2), "r"(a3), "r"(b0), "r"(b1));
}

__global__ __launch_bounds__(NTHR, 2) void mma_gemm_kernel(
    const __half* __restrict__ Ag, int lda,
    const __half* __restrict__ Bg, int ldb,
    float* __restrict__ out, int ldo, int ksteps,
    size_t slice_k, size_t out_slice)
{
    extern __shared__ __align__(1024) char sm[];
    const uint32_t smuA = smem_u32(sm);
    const uint32_t smuB = smuA + NSTAGE * ASTG;

    Ag  += (size_t)blockIdx.z * slice_k;
    Bg  += (size_t)blockIdx.z * slice_k;
    out += (size_t)blockIdx.z * out_slice;

    const int tid = threadIdx.x, lane = tid & 31, warp = tid >> 5;
    const int wm = warp & 1, wn = warp >> 1;          // 2 x 2 warp grid
    const int g = lane >> 2, tg = lane & 3;
    const int m0 = blockIdx.y * BM, n0 = blockIdx.x * BN;

    const int lrow = tid >> 3;                        // 0..15
    const int lkq  = tid & 7;                         // 16B granule in 128B row
    const uint32_t sgr = (lkq ^ swz(lrow & 7)) * 16;  // swizzled STS granule

    float c[4][8][4];
    #pragma unroll
    for (int i = 0; i < 4; i++)
        #pragma unroll
        for (int j = 0; j < 8; j++)
            #pragma unroll
            for (int k = 0; k < 4; k++) c[i][j][k] = 0.f;

    auto issue = [&](int kt, int s) {
        const __half* ab = Ag + (size_t)(m0 + lrow) * lda + (size_t)kt * BKH + lkq * 8;
        const __half* bb = Bg + (size_t)(n0 + lrow) * ldb + (size_t)kt * BKH + lkq * 8;
        #pragma unroll
        for (int i = 0; i < 8; i++)
            cp16(smuA + s * ASTG + (lrow + 16 * i) * 128 + sgr,
                 ab + (size_t)(16 * i) * lda);
        #pragma unroll
        for (int i = 0; i < 8; i++)
            cp16(smuB + s * BSTG + (lrow + 16 * i) * 128 + sgr,
                 bb + (size_t)(16 * i) * ldb);
    };

    #pragma unroll
    for (int s = 0; s < NSTAGE - 1; s++) {
        issue(s, s);
        asm volatile("cp.async.commit_group;" ::: "memory");
    }

    const uint32_t fsw = swz((uint32_t)g) * 16;       // fragment granule swizzle

    for (int kt = 0; kt < ksteps; kt++) {
        const int cur = kt % NSTAGE;
        asm volatile("cp.async.wait_group %0;" :: "n"(NSTAGE - 2) : "memory");
        __syncthreads();

        int nk = kt + NSTAGE - 1;
        if (nk < ksteps) issue(nk, nk % NSTAGE);
        asm volatile("cp.async.commit_group;" ::: "memory");

        const uint32_t sA = smuA + cur * ASTG + (wm * 64 + g) * 128;
        const uint32_t sB = smuB + cur * BSTG + (wn * 64 + g) * 128;

        // two k32 chunks per 128B stage row
        #pragma unroll
        for (int chk = 0; chk < 2; chk++) {
            const uint32_t goff = ((chk * 4 + tg) * 16) ^ fsw;
            uint4 alo[4], ahi[4], bv[8];
            #pragma unroll
            for (int im = 0; im < 4; im++) {
                uint32_t ra = sA + im * 16 * 128 + goff;
                alo[im] = lds128(ra);
                ahi[im] = lds128(ra + 8 * 128);
            }
            #pragma unroll
            for (int in = 0; in < 8; in++)
                bv[in] = lds128(sB + in * 8 * 128 + goff);

            // each uint4 covers two k16 groups: (.x,.y) and (.z,.w)
            #pragma unroll
            for (int im = 0; im < 4; im++)
                #pragma unroll
                for (int in = 0; in < 8; in++) {
                    mma16(c[im][in], alo[im].x, ahi[im].x, alo[im].y, ahi[im].y,
                          bv[in].x, bv[in].y);
                    mma16(c[im][in], alo[im].z, ahi[im].z, alo[im].w, ahi[im].w,
                          bv[in].z, bv[in].w);
                }
        }
    }

    // epilogue
    #pragma unroll
    for (int im = 0; im < 4; im++) {
        int row = m0 + wm * 64 + im * 16 + g;
        #pragma unroll
        for (int in = 0; in < 8; in++) {
            int col = n0 + wn * 64 + in * 8 + 2 * tg;
            float2 v0 = make_float2(c[im][in][0], c[im][in][1]);
            float2 v1 = make_float2(c[im][in][2], c[im][in][3]);
            *reinterpret_cast<float2*>(&out[(size_t)row * ldo + col])       = v0;
            *reinterpret_cast<float2*>(&out[(size_t)(row + 8) * ldo + col]) = v1;
        }
    }
}

// ---------------------------------------------------------------------------
// K5: finalize — reduce split-K partials, exact fp32 router logits, top-2
// gates, head softmax, u -> Xh[:, 4096:] (permuted). 16 tokens / block.
// ---------------------------------------------------------------------------
__global__ __launch_bounds__(512) void finalize_kernel(
    const float* __restrict__ x, const float* __restrict__ routerW)
{
    extern __shared__ float rw[];               // [NE * DIM] = 128KB
    __shared__ float scoeff[16][24];
    __shared__ float sP[16][160];

    const int tid = threadIdx.x, lane = tid & 31, warp = tid >> 5;
    const int token = blockIdx.x * 16 + warp;

    for (int i = tid; i < NE * DIM / 4; i += 512)
        reinterpret_cast<float4*>(rw)[i] = reinterpret_cast<const float4*>(routerW)[i];

    #pragma unroll
    for (int rep = 0; rep < 5; rep++) {
        int idx = lane + 32 * rep;
        float s = 0.f;
        #pragma unroll
        for (int sl = 0; sl < KSLICES; sl++)
            s += g_P4[((size_t)sl * N_TOK + token) * NWG + idx];
        sP[warp][idx] = s;
    }
    __syncthreads();

    float acc[NE];
    #pragma unroll
    for (int e = 0; e < NE; e++) acc[e] = 0.f;
    const float* xrow = x + (size_t)token * DIM;
    for (int i = lane; i < DIM; i += 32) {
        float xv = __ldg(xrow + i);
        #pragma unroll
        for (int e = 0; e < NE; e++) acc[e] += xv * rw[e * DIM + i];
    }
    #pragma unroll
    for (int e = 0; e < NE; e++)
        #pragma unroll
        for (int o = 16; o > 0; o >>= 1)
            acc[e] += __shfl_xor_sync(0xffffffffu, acc[e], o);

    if (lane == 0) {
        int i1 = 0;
        #pragma unroll
        for (int e = 1; e < NE; e++) if (acc[e] > acc[i1]) i1 = e;
        int i2 = (i1 == 0) ? 1 : 0;
        #pragma unroll
        for (int e = 0; e < NE; e++)
            if (e != i1 && acc[e] > acc[i2]) i2 = e;

        float ed = expf(acc[i2] - acc[i1]);
        float g1 = 1.f / (1.f + ed);
        float g2 = ed / (1.f + ed);

        #pragma unroll
        for (int q = 0; q < 24; q++) scoeff[warp][q] = 0.f;

        int   ids[2] = {i1, i2};
        float gs[2]  = {g1, g2};
        #pragma unroll
        for (int p = 0; p < 2; p++) {
            int e = ids[p];
            float h0 = sP[warp][128 + e * 3 + 0];
            float h1 = sP[warp][128 + e * 3 + 1];
            float h2 = sP[warp][128 + e * 3 + 2];
            float m  = fmaxf(h0, fmaxf(h1, h2));
            float x0 = expf(h0 - m), x1 = expf(h1 - m), x2 = expf(h2 - m);
            float inv = gs[p] * SCALE_F / (x0 + x1 + x2);
            scoeff[warp][e * 3 + 0] = x0 * inv;
            scoeff[warp][e * 3 + 1] = x1 * inv;
            scoeff[warp][e * 3 + 2] = x2 * inv;
        }
    }
    __syncwarp();

    #pragma unroll
    for (int rep = 0; rep < NU / 32; rep++) {
        int j = lane + 32 * rep;             // 0..383 (32-aligned groups)
        int e = j / 48;
        int jr = j - e * 48;
        int h = jr >> 4, r = jr & 15;
        float u = scoeff[warp][e * 3 + h] * sP[warp][e * 16 + r];
        g_Xh[(size_t)token * K_ALL + DIM + (j & ~31) + hperm32(j & 31)] =
            __float2half_rn(u);
    }
}

// ---------------------------------------------------------------------------
// host launch
// ---------------------------------------------------------------------------
extern "C" void kernel_launch(void* const* d_in, const int* in_sizes, int n_in,
                              void* d_out, int out_size) {
    const float* x       = (const float*)d_in[0];
    const float* baseW   = (const float*)d_in[1];
    const float* routerW = (const float*)d_in[2];
    const float* A       = (const float*)d_in[3];
    const float* B       = (const float*)d_in[4];
    const float* Rm      = (const float*)d_in[5];
    float* out = (float*)d_out;

    void *pXh = nullptr, *pWh = nullptr, *pWgh = nullptr, *pP4 = nullptr;
    cudaGetSymbolAddress(&pXh,  g_Xh);
    cudaGetSymbolAddress(&pWh,  g_Wh);
    cudaGetSymbolAddress(&pWgh, g_Wgh);
    cudaGetSymbolAddress(&pP4,  g_P4);

    static bool attr_set = false;
    if (!attr_set) {
        cudaFuncSetAttribute(mma_gemm_kernel,
                             cudaFuncAttributeMaxDynamicSharedMemorySize, SMEM_GEMM);
        cudaFuncSetAttribute(finalize_kernel,
                             cudaFuncAttributeMaxDynamicSharedMemorySize,
                             NE * DIM * sizeof(float));
        attr_set = true;
    }

    // 1) rn(x) -> Xh[:, :4096] (permuted fp16)
    round_x_kernel<<<(N_TOK * 128) / 256, 256>>>(x);
    // 2) rn([baseW;Bfl]^T) -> Wh
    transpose_w_kernel<<<dim3(K_ALL / 32, OUT_DIM / 32), 256>>>(baseW, B);
    // 3) gathered prep weights -> Wgh
    gather_wg_kernel<<<(NWG * DIM) / 256, 256>>>(A, Rm);
    // 4) prep GEMM, split-K=8: P4[s] = Xh[:, s-slice] @ Wgh[:, s-slice]^T
    {
        int stages = DIM / BKH / KSLICES;                 // 8
        size_t slice_k = (size_t)stages * BKH;            // 512 halves
        mma_gemm_kernel<<<dim3(NWG / BN, N_TOK / BM, KSLICES), NTHR, SMEM_GEMM>>>(
            (const __half*)pXh, K_ALL, (const __half*)pWgh, DIM,
            (float*)pP4, NWG, stages, slice_k, (size_t)N_TOK * NWG);
    }
    // 5) reduce partials + gates + head softmax + u -> Xh[:, 4096:]
    finalize_kernel<<<N_TOK / 16, 512, NE * DIM * sizeof(float)>>>(x, routerW);
    // 6) main GEMM: out = Xh @ Wh^T
    mma_gemm_kernel<<<dim3(OUT_DIM / BN, N_TOK / BM, 1), NTHR, SMEM_GEMM>>>(
        (const __half*)pXh, K_ALL, (const __half*)pWh, K_ALL,
        out, OUT_DIM, K_ALL / BKH, 0, 0);
}